// round 1
// baseline (speedup 1.0000x reference)
#include <cuda_runtime.h>

// Scratch (allocation-free rule: __device__ globals)
__device__ float g_hbuf[16 * 32 * 256];   // conv output h (b,c,l)
__device__ float g_scale[32];             // BN: rstd*gamma
__device__ float g_shift[32];             // BN: beta - mean*rstd*gamma

__device__ __forceinline__ float ex2f(float x) {
    float y;
    asm("ex2.approx.ftz.f32 %0, %1;" : "=f"(y) : "f"(x));
    return y;
}

// ---------------------------------------------------------------------------
// Kernel A: per (b,t) slice, t in [0,8): QKV proj + l2norm + attention + out
// proj, writing xo directly into out[:, :, t, :].
// grid = 128 blocks (b*8+t), 256 threads (one per token l).
// dyn smem: k4[8][256] f4 | v4[8][256] f4 | wq,wk,wv,wm[1024] | biases[128]
// ---------------------------------------------------------------------------
__global__ void __launch_bounds__(256) k_attn(
    const float* __restrict__ x,
    const float* __restrict__ qw, const float* __restrict__ qb,
    const float* __restrict__ kw, const float* __restrict__ kb,
    const float* __restrict__ vw, const float* __restrict__ vb,
    const float* __restrict__ mw, const float* __restrict__ mb,
    float* __restrict__ out)
{
    extern __shared__ float sm[];
    float4* k4 = (float4*)sm;                 // 8192 floats
    float4* v4 = (float4*)(sm + 8192);        // 8192 floats
    float* wq = sm + 16384;
    float* wk = wq + 1024;
    float* wv = wk + 1024;
    float* wm = wv + 1024;
    float* bb = wm + 1024;                    // [qb|kb|vb|mb] 4*32

    const int tid = threadIdx.x;              // token l
    const int t = blockIdx.x & 7;
    const int b = blockIdx.x >> 3;

    for (int i = tid; i < 1024; i += 256) {
        wq[i] = qw[i]; wk[i] = kw[i]; wv[i] = vw[i]; wm[i] = mw[i];
    }
    if (tid < 32) {
        bb[tid] = qb[tid]; bb[32 + tid] = kb[tid];
        bb[64 + tid] = vb[tid]; bb[96 + tid] = mb[tid];
    }

    // x[b, c, t, l] column into registers (coalesced over l)
    float xr[32];
    #pragma unroll
    for (int c = 0; c < 32; c++)
        xr[c] = x[((b * 32 + c) * 16 + t) * 256 + tid];

    __syncthreads();

    // QKV projections (weights broadcast from smem, float4 reads)
    float qreg[32], kr[32], vr[32];
    const float4* wq4 = (const float4*)wq;
    const float4* wk4 = (const float4*)wk;
    const float4* wv4 = (const float4*)wv;
    #pragma unroll
    for (int co = 0; co < 32; co++) {
        float aq = bb[co], ak = bb[32 + co], av = bb[64 + co];
        #pragma unroll
        for (int c4 = 0; c4 < 8; c4++) {
            float4 wqv = wq4[co * 8 + c4];
            float4 wkv = wk4[co * 8 + c4];
            float4 wvv = wv4[co * 8 + c4];
            float x0 = xr[4 * c4 + 0], x1 = xr[4 * c4 + 1];
            float x2 = xr[4 * c4 + 2], x3 = xr[4 * c4 + 3];
            aq += x0 * wqv.x + x1 * wqv.y + x2 * wqv.z + x3 * wqv.w;
            ak += x0 * wkv.x + x1 * wkv.y + x2 * wkv.z + x3 * wkv.w;
            av += x0 * wvv.x + x1 * wvv.y + x2 * wvv.z + x3 * wvv.w;
        }
        qreg[co] = aq; kr[co] = ak; vr[co] = av;
    }

    // per-head l2norm; fold (1/sqrt(hd)) * log2(e) into q
    const float QS = 0.5f * 1.4426950408889634f;
    #pragma unroll
    for (int h = 0; h < 8; h++) {
        float q0 = qreg[4*h+0], q1 = qreg[4*h+1], q2 = qreg[4*h+2], q3 = qreg[4*h+3];
        float qn = sqrtf(q0*q0 + q1*q1 + q2*q2 + q3*q3);
        float qi = QS / fmaxf(qn, 1e-12f);
        qreg[4*h+0] = q0*qi; qreg[4*h+1] = q1*qi; qreg[4*h+2] = q2*qi; qreg[4*h+3] = q3*qi;

        float k0 = kr[4*h+0], k1 = kr[4*h+1], k2 = kr[4*h+2], k3 = kr[4*h+3];
        float kn = sqrtf(k0*k0 + k1*k1 + k2*k2 + k3*k3);
        float ki = 1.0f / fmaxf(kn, 1e-12f);
        k4[h * 256 + tid] = make_float4(k0*ki, k1*ki, k2*ki, k3*ki);

        float v0 = vr[4*h+0], v1 = vr[4*h+1], v2 = vr[4*h+2], v3 = vr[4*h+3];
        float vn = sqrtf(v0*v0 + v1*v1 + v2*v2 + v3*v3);
        float vi = 1.0f / fmaxf(vn, 1e-12f);
        v4[h * 256 + tid] = make_float4(v0*vi, v1*vi, v2*vi, v3*vi);
    }
    __syncthreads();

    // attention: scores bounded in [-0.5,0.5] -> exp2 without max-subtraction
    float o[32];
    #pragma unroll
    for (int h = 0; h < 8; h++) {
        float q0 = qreg[4*h+0], q1 = qreg[4*h+1], q2 = qreg[4*h+2], q3 = qreg[4*h+3];
        float a0 = 0.f, a1 = 0.f, a2 = 0.f, a3 = 0.f, ssum = 0.f;
        const float4* kh = k4 + h * 256;
        const float4* vh = v4 + h * 256;
        #pragma unroll 4
        for (int m = 0; m < 256; m++) {
            float4 kk = kh[m];
            float s = q0 * kk.x + q1 * kk.y + q2 * kk.z + q3 * kk.w;
            float p = ex2f(s);
            float4 vv = vh[m];
            ssum += p;
            a0 += p * vv.x; a1 += p * vv.y; a2 += p * vv.z; a3 += p * vv.w;
        }
        float inv = 1.0f / ssum;
        o[4*h+0] = a0 * inv; o[4*h+1] = a1 * inv;
        o[4*h+2] = a2 * inv; o[4*h+3] = a3 * inv;
    }

    // output projection, write xo into out slot t
    const float4* wm4 = (const float4*)wm;
    #pragma unroll
    for (int co = 0; co < 32; co++) {
        float a = bb[96 + co];
        #pragma unroll
        for (int c4 = 0; c4 < 8; c4++) {
            float4 w = wm4[co * 8 + c4];
            a += o[4*c4+0] * w.x + o[4*c4+1] * w.y + o[4*c4+2] * w.z + o[4*c4+3] * w.w;
        }
        out[((b * 32 + co) * 9 + t) * 256 + tid] = a;
    }
}

// ---------------------------------------------------------------------------
// Kernel B: conv (9,1) VALID + bias -> g_hbuf. con = [xo t=0..7 | pre].
// grid = (4 cog, 16 b), 256 threads (l). Each block: 8 output channels.
// ---------------------------------------------------------------------------
__global__ void __launch_bounds__(256) k_conv(
    const float* __restrict__ out, const float* __restrict__ pre,
    const float* __restrict__ cw, const float* __restrict__ cb)
{
    __shared__ float cws[2304];   // [(ci*9+kt)*8 + j]
    __shared__ float cbs[8];
    const int tid = threadIdx.x;
    const int cog = blockIdx.x;
    const int b = blockIdx.y;

    for (int s = tid; s < 2304; s += 256) {
        int j = s & 7;
        int cikt = s >> 3;
        cws[s] = cw[cog * 2304 + j * 288 + cikt];
    }
    if (tid < 8) cbs[tid] = cb[cog * 8 + tid];
    __syncthreads();

    float acc[8];
    #pragma unroll
    for (int j = 0; j < 8; j++) acc[j] = cbs[j];

    for (int ci = 0; ci < 32; ci++) {
        #pragma unroll
        for (int kt = 0; kt < 9; kt++) {
            float v = (kt < 8) ? out[((b * 32 + ci) * 9 + kt) * 256 + tid]
                               : pre[ci * 256 + tid];
            float4 w0 = *(const float4*)&cws[(ci * 9 + kt) * 8];
            float4 w1 = *(const float4*)&cws[(ci * 9 + kt) * 8 + 4];
            acc[0] += v * w0.x; acc[1] += v * w0.y;
            acc[2] += v * w0.z; acc[3] += v * w0.w;
            acc[4] += v * w1.x; acc[5] += v * w1.y;
            acc[6] += v * w1.z; acc[7] += v * w1.w;
        }
    }
    #pragma unroll
    for (int j = 0; j < 8; j++)
        g_hbuf[(b * 32 + cog * 8 + j) * 256 + tid] = acc[j];
}

// ---------------------------------------------------------------------------
// Kernel C: BN batch stats per channel over (b,l) = 4096 elems.
// grid = 32 blocks (c), 128 threads.
// ---------------------------------------------------------------------------
__global__ void __launch_bounds__(128) k_stats(
    const float* __restrict__ gamma, const float* __restrict__ beta)
{
    __shared__ float rs[128], rs2[128];
    const int c = blockIdx.x, tid = threadIdx.x;
    float s = 0.f, s2 = 0.f;
    for (int e = tid; e < 4096; e += 128) {
        float v = g_hbuf[(e >> 8) * 8192 + c * 256 + (e & 255)];
        s += v; s2 += v * v;
    }
    rs[tid] = s; rs2[tid] = s2;
    __syncthreads();
    for (int off = 64; off > 0; off >>= 1) {
        if (tid < off) { rs[tid] += rs[tid + off]; rs2[tid] += rs2[tid + off]; }
        __syncthreads();
    }
    if (tid == 0) {
        float mean = rs[0] * (1.0f / 4096.0f);
        float var = rs2[0] * (1.0f / 4096.0f) - mean * mean;
        float rstd = rsqrtf(var + 1e-5f);
        float sc = rstd * gamma[c];
        g_scale[c] = sc;
        g_shift[c] = beta[c] - mean * sc;
    }
}

// ---------------------------------------------------------------------------
// Kernel D: BN+ReLU, linear over l (256x256), p = xo[:,:,2] - p -> out slot 8.
// grid = (32 c, 2 bg), 256 threads (l'). lin_w tiled through smem, pad 33.
// ---------------------------------------------------------------------------
__global__ void __launch_bounds__(256) k_lin(
    const float* __restrict__ lw, const float* __restrict__ lb,
    float* __restrict__ out)
{
    __shared__ float hbn[8 * 256];
    __shared__ float lws[256 * 33];
    const int c = blockIdx.x, bg = blockIdx.y, tid = threadIdx.x;
    const int lane = tid & 31, wrp = tid >> 5;

    float sc = g_scale[c], sh = g_shift[c];
    #pragma unroll
    for (int r = 0; r < 8; r++) {
        int b = bg * 8 + r;
        hbn[r * 256 + tid] = fmaxf(g_hbuf[(b * 32 + c) * 256 + tid] * sc + sh, 0.f);
    }

    float acc[8] = {0.f, 0.f, 0.f, 0.f, 0.f, 0.f, 0.f, 0.f};
    for (int tile = 0; tile < 8; tile++) {
        __syncthreads();
        // coalesced lin_w tile load: rows rr, cols [tile*32, tile*32+32)
        for (int rr = wrp; rr < 256; rr += 8)
            lws[rr * 33 + lane] = lw[rr * 256 + tile * 32 + lane];
        __syncthreads();
        #pragma unroll
        for (int i = 0; i < 32; i++) {
            float w = lws[tid * 33 + i];       // bank (tid+i)%32: conflict-free
            int l = tile * 32 + i;
            #pragma unroll
            for (int r = 0; r < 8; r++)
                acc[r] += hbn[r * 256 + l] * w; // broadcast
        }
    }

    float lbv = lb[tid];
    #pragma unroll
    for (int r = 0; r < 8; r++) {
        int b = bg * 8 + r;
        int base = (b * 32 + c) * 9;
        out[(base + 8) * 256 + tid] = out[(base + 2) * 256 + tid] - (acc[r] + lbv);
    }
}

// ---------------------------------------------------------------------------
extern "C" void kernel_launch(void* const* d_in, const int* in_sizes, int n_in,
                              void* d_out, int out_size)
{
    const float* x     = (const float*)d_in[0];
    const float* qw    = (const float*)d_in[1];
    const float* qb    = (const float*)d_in[2];
    const float* kw    = (const float*)d_in[3];
    const float* kb    = (const float*)d_in[4];
    const float* vw    = (const float*)d_in[5];
    const float* vb    = (const float*)d_in[6];
    const float* mw    = (const float*)d_in[7];
    const float* mb    = (const float*)d_in[8];
    const float* pre   = (const float*)d_in[9];
    const float* cw    = (const float*)d_in[10];
    const float* cb    = (const float*)d_in[11];
    const float* gamma = (const float*)d_in[12];
    const float* beta  = (const float*)d_in[13];
    const float* lw    = (const float*)d_in[14];
    const float* lb    = (const float*)d_in[15];
    // d_in[16] = atten_flag (unused by reference math)
    float* out = (float*)d_out;

    const int smemA = (8192 + 8192 + 4096 + 128) * 4;  // 82432 B
    cudaFuncSetAttribute(k_attn, cudaFuncAttributeMaxDynamicSharedMemorySize, smemA);

    k_attn<<<128, 256, smemA>>>(x, qw, qb, kw, kb, vw, vb, mw, mb, out);
    k_conv<<<dim3(4, 16), 256>>>(out, pre, cw, cb);
    k_stats<<<32, 128>>>(gamma, beta);
    k_lin<<<dim3(32, 2), 256>>>(lw, lb, out);
}

// round 2
// speedup vs baseline: 1.2160x; 1.2160x over previous
#include <cuda_runtime.h>

// Scratch (allocation-free rule: __device__ globals)
__device__ float g_hbuf[16 * 32 * 256];   // conv output h (b,c,l)
__device__ float g_scale[32];             // BN: rstd*gamma
__device__ float g_shift[32];             // BN: beta - mean*rstd*gamma

typedef unsigned long long ull;

__device__ __forceinline__ float ex2f(float x) {
    float y;
    asm("ex2.approx.ftz.f32 %0, %1;" : "=f"(y) : "f"(x));
    return y;
}
__device__ __forceinline__ ull pk(float a, float b) {
    ull r; asm("mov.b64 %0, {%1, %2};" : "=l"(r) : "f"(a), "f"(b)); return r;
}
__device__ __forceinline__ void upk(ull x, float& a, float& b) {
    asm("mov.b64 {%0, %1}, %2;" : "=f"(a), "=f"(b) : "l"(x));
}
__device__ __forceinline__ ull fma2(ull a, ull b, ull c) {
    ull r; asm("fma.rn.f32x2 %0, %1, %2, %3;" : "=l"(r) : "l"(a), "l"(b), "l"(c)); return r;
}
__device__ __forceinline__ ull mul2(ull a, ull b) {
    ull r; asm("mul.rn.f32x2 %0, %1, %2;" : "=l"(r) : "l"(a), "l"(b)); return r;
}
__device__ __forceinline__ ull add2(ull a, ull b) {
    ull r; asm("add.rn.f32x2 %0, %1, %2;" : "=l"(r) : "l"(a), "l"(b)); return r;
}
__device__ __forceinline__ float hsum(ull x) {
    float a, b; upk(x, a, b); return a + b;
}

// ---------------------------------------------------------------------------
// Kernel A: per (b,t) slice, t in [0,8): QKV proj + l2norm + attention + out
// proj, writing xo directly into out[:, :, t, :]. Packed f32x2 math.
// grid = 128 blocks (b*8+t), 256 threads (one per token l).
// ---------------------------------------------------------------------------
__global__ void __launch_bounds__(256) k_attn(
    const float* __restrict__ x,
    const float* __restrict__ qw, const float* __restrict__ qb,
    const float* __restrict__ kw, const float* __restrict__ kb,
    const float* __restrict__ vw, const float* __restrict__ vb,
    const float* __restrict__ mw, const float* __restrict__ mb,
    float* __restrict__ out)
{
    extern __shared__ float sm[];
    float4* k4 = (float4*)sm;                 // 8192 floats
    float4* v4 = (float4*)(sm + 8192);        // 8192 floats
    float* wq = sm + 16384;
    float* wk = wq + 1024;
    float* wv = wk + 1024;
    float* wm = wv + 1024;
    float* bb = wm + 1024;                    // [qb|kb|vb|mb] 4*32

    const int tid = threadIdx.x;              // token l
    const int t = blockIdx.x & 7;
    const int b = blockIdx.x >> 3;

    for (int i = tid; i < 1024; i += 256) {
        wq[i] = qw[i]; wk[i] = kw[i]; wv[i] = vw[i]; wm[i] = mw[i];
    }
    if (tid < 32) {
        bb[tid] = qb[tid]; bb[32 + tid] = kb[tid];
        bb[64 + tid] = vb[tid]; bb[96 + tid] = mb[tid];
    }

    // x[b, c, t, l] column into registers (coalesced over l)
    float xr[32];
    #pragma unroll
    for (int c = 0; c < 32; c++)
        xr[c] = x[((b * 32 + c) * 16 + t) * 256 + tid];

    __syncthreads();

    // pack x into f32x2 pairs
    ull xp[16];
    #pragma unroll
    for (int i = 0; i < 16; i++) xp[i] = pk(xr[2 * i], xr[2 * i + 1]);

    const ulonglong2* wq2 = (const ulonglong2*)wq;   // row co: 8 ull2
    const ulonglong2* wk2 = (const ulonglong2*)wk;
    const ulonglong2* wv2 = (const ulonglong2*)wv;

    // per-head: QKV proj (packed) + l2norm; fold (1/sqrt(hd))*log2(e) into q
    const float QS = 0.5f * 1.4426950408889634f;
    ull qp[16];
    #pragma unroll
    for (int h = 0; h < 8; h++) {
        float qv[4], kv[4], vv[4];
        #pragma unroll
        for (int j = 0; j < 4; j++) {
            int co = h * 4 + j;
            ull a0 = 0, a1 = 0, b0 = 0, b1 = 0, c0 = 0, c1 = 0;
            #pragma unroll
            for (int c4 = 0; c4 < 8; c4++) {
                ulonglong2 w = wq2[co * 8 + c4];
                a0 = fma2(xp[2 * c4], w.x, a0);
                a1 = fma2(xp[2 * c4 + 1], w.y, a1);
                w = wk2[co * 8 + c4];
                b0 = fma2(xp[2 * c4], w.x, b0);
                b1 = fma2(xp[2 * c4 + 1], w.y, b1);
                w = wv2[co * 8 + c4];
                c0 = fma2(xp[2 * c4], w.x, c0);
                c1 = fma2(xp[2 * c4 + 1], w.y, c1);
            }
            qv[j] = hsum(add2(a0, a1)) + bb[co];
            kv[j] = hsum(add2(b0, b1)) + bb[32 + co];
            vv[j] = hsum(add2(c0, c1)) + bb[64 + co];
        }
        float qn = sqrtf(qv[0]*qv[0] + qv[1]*qv[1] + qv[2]*qv[2] + qv[3]*qv[3]);
        float qi = QS / fmaxf(qn, 1e-12f);
        qp[2 * h]     = pk(qv[0] * qi, qv[1] * qi);
        qp[2 * h + 1] = pk(qv[2] * qi, qv[3] * qi);

        float kn = sqrtf(kv[0]*kv[0] + kv[1]*kv[1] + kv[2]*kv[2] + kv[3]*kv[3]);
        float ki = 1.0f / fmaxf(kn, 1e-12f);
        k4[h * 256 + tid] = make_float4(kv[0]*ki, kv[1]*ki, kv[2]*ki, kv[3]*ki);

        float vn = sqrtf(vv[0]*vv[0] + vv[1]*vv[1] + vv[2]*vv[2] + vv[3]*vv[3]);
        float vi = 1.0f / fmaxf(vn, 1e-12f);
        v4[h * 256 + tid] = make_float4(vv[0]*vi, vv[1]*vi, vv[2]*vi, vv[3]*vi);
    }
    __syncthreads();

    // attention: scores in [-0.5,0.5] -> exp2 without max-subtraction.
    // packed f32x2 dot + accumulate.
    ull op[16];
    #pragma unroll
    for (int h = 0; h < 8; h++) {
        ull q01 = qp[2 * h], q23 = qp[2 * h + 1];
        ull a01 = 0, a23 = 0;
        float ssum = 0.f;
        const ulonglong2* kh = (const ulonglong2*)(k4 + h * 256);
        const ulonglong2* vh = (const ulonglong2*)(v4 + h * 256);
        #pragma unroll 8
        for (int m = 0; m < 256; m++) {
            ulonglong2 kk = kh[m];
            ull tt = fma2(q23, kk.y, mul2(q01, kk.x));
            float p = ex2f(hsum(tt));
            ulonglong2 vm = vh[m];
            ull pp = pk(p, p);
            a01 = fma2(pp, vm.x, a01);
            a23 = fma2(pp, vm.y, a23);
            ssum += p;
        }
        float inv = 1.0f / ssum;
        ull ii = pk(inv, inv);
        op[2 * h]     = mul2(a01, ii);
        op[2 * h + 1] = mul2(a23, ii);
    }

    // output projection (packed), write xo into out slot t
    const ulonglong2* wm2 = (const ulonglong2*)wm;
    #pragma unroll
    for (int co = 0; co < 32; co++) {
        ull a0 = 0, a1 = 0;
        #pragma unroll
        for (int c4 = 0; c4 < 8; c4++) {
            ulonglong2 w = wm2[co * 8 + c4];
            a0 = fma2(op[2 * c4], w.x, a0);
            a1 = fma2(op[2 * c4 + 1], w.y, a1);
        }
        out[((b * 32 + co) * 9 + t) * 256 + tid] = hsum(add2(a0, a1)) + bb[96 + co];
    }
}

// ---------------------------------------------------------------------------
// Kernel B: conv (9,1) VALID + bias -> g_hbuf. con = [xo t=0..7 | pre].
// grid = (4 cog, 16 b), 256 threads (l). Each block: 8 output channels.
// ---------------------------------------------------------------------------
__global__ void __launch_bounds__(256) k_conv(
    const float* __restrict__ out, const float* __restrict__ pre,
    const float* __restrict__ cw, const float* __restrict__ cb)
{
    __shared__ float cws[2304];   // [(ci*9+kt)*8 + j]
    __shared__ float cbs[8];
    const int tid = threadIdx.x;
    const int cog = blockIdx.x;
    const int b = blockIdx.y;

    for (int s = tid; s < 2304; s += 256) {
        int j = s & 7;
        int cikt = s >> 3;
        cws[s] = cw[cog * 2304 + j * 288 + cikt];
    }
    if (tid < 8) cbs[tid] = cb[cog * 8 + tid];
    __syncthreads();

    float acc[8];
    #pragma unroll
    for (int j = 0; j < 8; j++) acc[j] = cbs[j];

    for (int ci = 0; ci < 32; ci++) {
        #pragma unroll
        for (int kt = 0; kt < 9; kt++) {
            float v = (kt < 8) ? out[((b * 32 + ci) * 9 + kt) * 256 + tid]
                               : pre[ci * 256 + tid];
            float4 w0 = *(const float4*)&cws[(ci * 9 + kt) * 8];
            float4 w1 = *(const float4*)&cws[(ci * 9 + kt) * 8 + 4];
            acc[0] += v * w0.x; acc[1] += v * w0.y;
            acc[2] += v * w0.z; acc[3] += v * w0.w;
            acc[4] += v * w1.x; acc[5] += v * w1.y;
            acc[6] += v * w1.z; acc[7] += v * w1.w;
        }
    }
    #pragma unroll
    for (int j = 0; j < 8; j++)
        g_hbuf[(b * 32 + cog * 8 + j) * 256 + tid] = acc[j];
}

// ---------------------------------------------------------------------------
// Kernel C: BN batch stats per channel over (b,l) = 4096 elems.
// grid = 32 blocks (c), 128 threads.
// ---------------------------------------------------------------------------
__global__ void __launch_bounds__(128) k_stats(
    const float* __restrict__ gamma, const float* __restrict__ beta)
{
    __shared__ float rs[128], rs2[128];
    const int c = blockIdx.x, tid = threadIdx.x;
    float s = 0.f, s2 = 0.f;
    for (int e = tid; e < 4096; e += 128) {
        float v = g_hbuf[(e >> 8) * 8192 + c * 256 + (e & 255)];
        s += v; s2 += v * v;
    }
    rs[tid] = s; rs2[tid] = s2;
    __syncthreads();
    for (int off = 64; off > 0; off >>= 1) {
        if (tid < off) { rs[tid] += rs[tid + off]; rs2[tid] += rs2[tid + off]; }
        __syncthreads();
    }
    if (tid == 0) {
        float mean = rs[0] * (1.0f / 4096.0f);
        float var = rs2[0] * (1.0f / 4096.0f) - mean * mean;
        float rstd = rsqrtf(var + 1e-5f);
        float sc = rstd * gamma[c];
        g_scale[c] = sc;
        g_shift[c] = beta[c] - mean * sc;
    }
}

// ---------------------------------------------------------------------------
// Kernel D: BN+ReLU, linear over l (256x256), p = xo[:,:,2] - p -> out slot 8.
// grid = (8 l'-tiles, 16 b), 256 threads. Thread (cq=tid>>5, lane) computes
// 4 channels x 1 l'. lin_w tile [32 l' x 256 l] staged in smem (stride 260
// floats = 65x16B odd -> conflict-free LDS128). hbn reads are broadcasts.
// ---------------------------------------------------------------------------
__global__ void __launch_bounds__(256) k_lin(
    const float* __restrict__ lw, const float* __restrict__ lb,
    float* __restrict__ out)
{
    extern __shared__ float smd[];
    float* hbn = smd;            // [32][256]
    float* lws = smd + 8192;     // [32][260]

    const int tid = threadIdx.x;
    const int lane = tid & 31, cq = tid >> 5;
    const int lt = blockIdx.x;   // l'-tile
    const int b = blockIdx.y;

    // hbn: BN + ReLU applied on load (per-iteration c is uniform -> LDG bcast)
    #pragma unroll 4
    for (int c = 0; c < 32; c++) {
        float v = g_hbuf[(b * 32 + c) * 256 + tid];
        hbn[c * 256 + tid] = fmaxf(v * g_scale[c] + g_shift[c], 0.f);
    }
    // lin_w tile rows l' = lt*32 + r, all 256 cols (coalesced)
    #pragma unroll 4
    for (int r = 0; r < 32; r++)
        lws[r * 260 + tid] = lw[(lt * 32 + r) * 256 + tid];
    __syncthreads();

    const int c0 = cq * 4;
    ull acc[4] = {0, 0, 0, 0};
    const ulonglong2* wrow = (const ulonglong2*)&lws[lane * 260];
    const ulonglong2* h0 = (const ulonglong2*)&hbn[(c0 + 0) * 256];
    const ulonglong2* h1 = (const ulonglong2*)&hbn[(c0 + 1) * 256];
    const ulonglong2* h2 = (const ulonglong2*)&hbn[(c0 + 2) * 256];
    const ulonglong2* h3 = (const ulonglong2*)&hbn[(c0 + 3) * 256];
    #pragma unroll 8
    for (int l4 = 0; l4 < 64; l4++) {
        ulonglong2 w = wrow[l4];
        ulonglong2 a = h0[l4], bq = h1[l4], cc = h2[l4], d = h3[l4];
        acc[0] = fma2(w.x, a.x,  acc[0]); acc[0] = fma2(w.y, a.y,  acc[0]);
        acc[1] = fma2(w.x, bq.x, acc[1]); acc[1] = fma2(w.y, bq.y, acc[1]);
        acc[2] = fma2(w.x, cc.x, acc[2]); acc[2] = fma2(w.y, cc.y, acc[2]);
        acc[3] = fma2(w.x, d.x,  acc[3]); acc[3] = fma2(w.y, d.y,  acc[3]);
    }

    const int lp = lt * 32 + lane;
    const float lbv = lb[lp];
    #pragma unroll
    for (int j = 0; j < 4; j++) {
        int base = (b * 32 + c0 + j) * 9;
        float p = hsum(acc[j]) + lbv;
        out[(base + 8) * 256 + lp] = out[(base + 2) * 256 + lp] - p;
    }
}

// ---------------------------------------------------------------------------
extern "C" void kernel_launch(void* const* d_in, const int* in_sizes, int n_in,
                              void* d_out, int out_size)
{
    const float* x     = (const float*)d_in[0];
    const float* qw    = (const float*)d_in[1];
    const float* qb    = (const float*)d_in[2];
    const float* kw    = (const float*)d_in[3];
    const float* kb    = (const float*)d_in[4];
    const float* vw    = (const float*)d_in[5];
    const float* vb    = (const float*)d_in[6];
    const float* mw    = (const float*)d_in[7];
    const float* mb    = (const float*)d_in[8];
    const float* pre   = (const float*)d_in[9];
    const float* cw    = (const float*)d_in[10];
    const float* cb    = (const float*)d_in[11];
    const float* gamma = (const float*)d_in[12];
    const float* beta  = (const float*)d_in[13];
    const float* lw    = (const float*)d_in[14];
    const float* lb    = (const float*)d_in[15];
    float* out = (float*)d_out;

    const int smemA = (8192 + 8192 + 4096 + 128) * 4;  // 82432 B
    cudaFuncSetAttribute(k_attn, cudaFuncAttributeMaxDynamicSharedMemorySize, smemA);
    const int smemD = (8192 + 32 * 260) * 4;           // 66048 B
    cudaFuncSetAttribute(k_lin, cudaFuncAttributeMaxDynamicSharedMemorySize, smemD);

    k_attn<<<128, 256, smemA>>>(x, qw, qb, kw, kb, vw, vb, mw, mb, out);
    k_conv<<<dim3(4, 16), 256>>>(out, pre, cw, cb);
    k_stats<<<32, 128>>>(gamma, beta);
    k_lin<<<dim3(8, 16), 256, smemD>>>(lw, lb, out);
}

// round 3
// speedup vs baseline: 1.3263x; 1.0908x over previous
#include <cuda_runtime.h>

// Scratch (allocation-free rule: __device__ globals)
__device__ float g_hbuf[16 * 32 * 256];   // conv output h (b,c,l)
__device__ float g_scale[32];             // BN: rstd*gamma
__device__ float g_shift[32];             // BN: beta - mean*rstd*gamma

typedef unsigned long long ull;

__device__ __forceinline__ float ex2f(float x) {
    float y;
    asm("ex2.approx.ftz.f32 %0, %1;" : "=f"(y) : "f"(x));
    return y;
}
__device__ __forceinline__ ull pk(float a, float b) {
    ull r; asm("mov.b64 %0, {%1, %2};" : "=l"(r) : "f"(a), "f"(b)); return r;
}
__device__ __forceinline__ void upk(ull x, float& a, float& b) {
    asm("mov.b64 {%0, %1}, %2;" : "=f"(a), "=f"(b) : "l"(x));
}
__device__ __forceinline__ ull fma2(ull a, ull b, ull c) {
    ull r; asm("fma.rn.f32x2 %0, %1, %2, %3;" : "=l"(r) : "l"(a), "l"(b), "l"(c)); return r;
}
__device__ __forceinline__ ull mul2(ull a, ull b) {
    ull r; asm("mul.rn.f32x2 %0, %1, %2;" : "=l"(r) : "l"(a), "l"(b)); return r;
}
__device__ __forceinline__ ull add2(ull a, ull b) {
    ull r; asm("add.rn.f32x2 %0, %1, %2;" : "=l"(r) : "l"(a), "l"(b)); return r;
}
__device__ __forceinline__ float hsum(ull x) {
    float a, b; upk(x, a, b); return a + b;
}

// ---------------------------------------------------------------------------
// Kernel A: per (b,t) slice, t in [0,8). 512 threads: thread = (token, head
// group of 4). QKV proj (packed) -> K/V to smem in d-major m-pair-interleaved
// layout -> attention with broadcast LDS.128 + split score tree -> o staged
// in smem -> out proj. grid = 128 blocks.
// smem (floats): kbuf 8192 | vbuf 8192 | wq,wk,wv,wm 4096 | bb 128 | osm 8704
// ---------------------------------------------------------------------------
__global__ void __launch_bounds__(512) k_attn(
    const float* __restrict__ x,
    const float* __restrict__ qw, const float* __restrict__ qb,
    const float* __restrict__ kw, const float* __restrict__ kb,
    const float* __restrict__ vw, const float* __restrict__ vb,
    const float* __restrict__ mw, const float* __restrict__ mb,
    float* __restrict__ out)
{
    extern __shared__ float sm[];
    float* kbuf = sm;                  // [8 h][128 mp][8]: k0m0,k0m1,k1m0,k1m1,k2m0,k2m1,k3m0,k3m1
    float* vbuf = sm + 8192;
    float* wq = sm + 16384;
    float* wk = wq + 1024;
    float* wv = wk + 1024;
    float* wm = wv + 1024;
    float* bb = wm + 1024;             // [qb|kb|vb|mb]
    ull*   osm = (ull*)(sm + 20608);   // [256 tok][17] ull (16 used, stride 17)

    const int tid = threadIdx.x;
    const int tok = tid & 255;
    const int hg  = tid >> 8;          // head group: 0 -> h0..3, 1 -> h4..7
    const int t = blockIdx.x & 7;
    const int b = blockIdx.x >> 3;

    for (int i = tid; i < 1024; i += 512) {
        wq[i] = qw[i]; wk[i] = kw[i]; wv[i] = vw[i]; wm[i] = mw[i];
    }
    if (tid < 32) {
        bb[tid] = qb[tid]; bb[32 + tid] = kb[tid];
        bb[64 + tid] = vb[tid]; bb[96 + tid] = mb[tid];
    }

    // x[b, c, t, tok] column (coalesced over tok; both halves load it)
    float xr[32];
    #pragma unroll
    for (int c = 0; c < 32; c++)
        xr[c] = x[((b * 32 + c) * 16 + t) * 256 + tok];

    __syncthreads();

    ull xp[16];
    #pragma unroll
    for (int i = 0; i < 16; i++) xp[i] = pk(xr[2 * i], xr[2 * i + 1]);

    const ulonglong2* wq2 = (const ulonglong2*)wq;   // row co: 8 ull2
    const ulonglong2* wk2 = (const ulonglong2*)wk;
    const ulonglong2* wv2 = (const ulonglong2*)wv;

    // QKV for my 4 heads; fold (1/sqrt(hd))*log2(e) into q
    const float QS = 0.5f * 1.4426950408889634f;
    ull qp[8];
    #pragma unroll
    for (int hh = 0; hh < 4; hh++) {
        const int h = hg * 4 + hh;
        float qv[4], kv[4], vv[4];
        #pragma unroll
        for (int j = 0; j < 4; j++) {
            const int co = h * 4 + j;
            ull a0 = 0, a1 = 0, b0 = 0, b1 = 0, c0 = 0, c1 = 0;
            #pragma unroll
            for (int c4 = 0; c4 < 8; c4++) {
                ulonglong2 w = wq2[co * 8 + c4];
                a0 = fma2(xp[2 * c4], w.x, a0);
                a1 = fma2(xp[2 * c4 + 1], w.y, a1);
                w = wk2[co * 8 + c4];
                b0 = fma2(xp[2 * c4], w.x, b0);
                b1 = fma2(xp[2 * c4 + 1], w.y, b1);
                w = wv2[co * 8 + c4];
                c0 = fma2(xp[2 * c4], w.x, c0);
                c1 = fma2(xp[2 * c4 + 1], w.y, c1);
            }
            qv[j] = hsum(add2(a0, a1)) + bb[co];
            kv[j] = hsum(add2(b0, b1)) + bb[32 + co];
            vv[j] = hsum(add2(c0, c1)) + bb[64 + co];
        }
        float qn = sqrtf(qv[0]*qv[0] + qv[1]*qv[1] + qv[2]*qv[2] + qv[3]*qv[3]);
        float qi = QS / fmaxf(qn, 1e-12f);
        qp[2 * hh]     = pk(qv[0] * qi, qv[1] * qi);
        qp[2 * hh + 1] = pk(qv[2] * qi, qv[3] * qi);

        float kn = sqrtf(kv[0]*kv[0] + kv[1]*kv[1] + kv[2]*kv[2] + kv[3]*kv[3]);
        float ki = 1.0f / fmaxf(kn, 1e-12f);
        float vn = sqrtf(vv[0]*vv[0] + vv[1]*vv[1] + vv[2]*vv[2] + vv[3]*vv[3]);
        float vi = 1.0f / fmaxf(vn, 1e-12f);

        const int base = h * 1024 + (tok >> 1) * 8 + (tok & 1);
        #pragma unroll
        for (int d = 0; d < 4; d++) {
            kbuf[base + 2 * d] = kv[d] * ki;
            vbuf[base + 2 * d] = vv[d] * vi;
        }
    }
    __syncthreads();

    // attention for my 4 heads; scores in [-0.5,0.5] -> exp2, no max pass.
    // All smem reads are warp-uniform broadcasts (LDS.128, N=1).
    #pragma unroll
    for (int hh = 0; hh < 4; hh++) {
        const int h = hg * 4 + hh;
        const ulonglong2* kb2 = (const ulonglong2*)(kbuf + h * 1024);
        const ulonglong2* vb2 = (const ulonglong2*)(vbuf + h * 1024);
        const ull qq0 = qp[2 * hh], qq1 = qp[2 * hh + 1];
        float q0, q1, q2, q3;
        upk(qq0, q0, q1); upk(qq1, q2, q3);
        const ull Q0 = pk(q0, q0), Q1 = pk(q1, q1), Q2 = pk(q2, q2), Q3 = pk(q3, q3);

        ull pa0 = 0, pa1 = 0, pa2 = 0, pa3 = 0, ss = 0;
        #pragma unroll 4
        for (int mp = 0; mp < 128; mp++) {
            ulonglong2 KA = kb2[2 * mp];       // (k0 pair, k1 pair)
            ulonglong2 KB = kb2[2 * mp + 1];   // (k2 pair, k3 pair)
            ull sA = mul2(Q0, KA.x);
            ull sB = mul2(Q2, KB.x);
            sA = fma2(Q1, KA.y, sA);
            sB = fma2(Q3, KB.y, sB);
            ull s = add2(sA, sB);
            float s0, s1; upk(s, s0, s1);
            ull pp = pk(ex2f(s0), ex2f(s1));
            ulonglong2 VA = vb2[2 * mp];
            ulonglong2 VB = vb2[2 * mp + 1];
            ss = add2(ss, pp);
            pa0 = fma2(pp, VA.x, pa0);
            pa1 = fma2(pp, VA.y, pa1);
            pa2 = fma2(pp, VB.x, pa2);
            pa3 = fma2(pp, VB.y, pa3);
        }
        float inv = 1.0f / hsum(ss);
        osm[tok * 17 + hg * 8 + 2 * hh]     = pk(hsum(pa0) * inv, hsum(pa1) * inv);
        osm[tok * 17 + hg * 8 + 2 * hh + 1] = pk(hsum(pa2) * inv, hsum(pa3) * inv);
    }
    __syncthreads();

    // out projection: thread handles 16 co channels for its token.
    ull ov[16];
    #pragma unroll
    for (int i = 0; i < 16; i++) ov[i] = osm[tok * 17 + i];

    const ull* wmu = (const ull*)wm;   // row co: 16 ull (warp-uniform reads)
    #pragma unroll
    for (int j = 0; j < 16; j++) {
        const int co = hg * 16 + j;
        ull a0 = 0, a1 = 0;
        #pragma unroll
        for (int i = 0; i < 16; i += 2) {
            a0 = fma2(ov[i],     wmu[co * 16 + i],     a0);
            a1 = fma2(ov[i + 1], wmu[co * 16 + i + 1], a1);
        }
        out[((b * 32 + co) * 9 + t) * 256 + tok] = hsum(add2(a0, a1)) + bb[96 + co];
    }
}

// ---------------------------------------------------------------------------
// Kernel B: conv (9,1) VALID + bias -> g_hbuf. con = [xo t=0..7 | pre].
// grid = (8 cog, 16 b), 256 threads (l). Each block: 4 output channels.
// ---------------------------------------------------------------------------
__global__ void __launch_bounds__(256) k_conv(
    const float* __restrict__ out, const float* __restrict__ pre,
    const float* __restrict__ cw, const float* __restrict__ cb)
{
    __shared__ float cws[1152];   // [(ci*9+kt)*4 + j]
    __shared__ float cbs[4];
    const int tid = threadIdx.x;
    const int cog = blockIdx.x;
    const int b = blockIdx.y;

    for (int s = tid; s < 1152; s += 256) {
        int j = s & 3;
        int cikt = s >> 2;
        cws[s] = cw[cog * 1152 + j * 288 + cikt];
    }
    if (tid < 4) cbs[tid] = cb[cog * 4 + tid];
    __syncthreads();

    float acc[4];
    #pragma unroll
    for (int j = 0; j < 4; j++) acc[j] = cbs[j];

    for (int ci = 0; ci < 32; ci++) {
        #pragma unroll
        for (int kt = 0; kt < 9; kt++) {
            float v = (kt < 8) ? out[((b * 32 + ci) * 9 + kt) * 256 + tid]
                               : pre[ci * 256 + tid];
            float4 w = *(const float4*)&cws[(ci * 9 + kt) * 4];
            acc[0] += v * w.x; acc[1] += v * w.y;
            acc[2] += v * w.z; acc[3] += v * w.w;
        }
    }
    #pragma unroll
    for (int j = 0; j < 4; j++)
        g_hbuf[(b * 32 + cog * 4 + j) * 256 + tid] = acc[j];
}

// ---------------------------------------------------------------------------
// Kernel C: BN batch stats per channel over (b,l) = 4096 elems.
// grid = 32 blocks (c), 128 threads.
// ---------------------------------------------------------------------------
__global__ void __launch_bounds__(128) k_stats(
    const float* __restrict__ gamma, const float* __restrict__ beta)
{
    __shared__ float rs[128], rs2[128];
    const int c = blockIdx.x, tid = threadIdx.x;
    float s = 0.f, s2 = 0.f;
    for (int e = tid; e < 4096; e += 128) {
        float v = g_hbuf[(e >> 8) * 8192 + c * 256 + (e & 255)];
        s += v; s2 += v * v;
    }
    rs[tid] = s; rs2[tid] = s2;
    __syncthreads();
    for (int off = 64; off > 0; off >>= 1) {
        if (tid < off) { rs[tid] += rs[tid + off]; rs2[tid] += rs2[tid + off]; }
        __syncthreads();
    }
    if (tid == 0) {
        float mean = rs[0] * (1.0f / 4096.0f);
        float var = rs2[0] * (1.0f / 4096.0f) - mean * mean;
        float rstd = rsqrtf(var + 1e-5f);
        float sc = rstd * gamma[c];
        g_scale[c] = sc;
        g_shift[c] = beta[c] - mean * sc;
    }
}

// ---------------------------------------------------------------------------
// Kernel D: BN+ReLU, linear over l (256x256), p = xo[:,:,2] - p -> out slot 8.
// grid = (8 l'-tiles, 16 b), 512 threads. Thread (cq=tid>>5, lane) computes
// 2 channels x 1 l'. lin_w tile in smem (stride 260 floats).
// ---------------------------------------------------------------------------
__global__ void __launch_bounds__(512) k_lin(
    const float* __restrict__ lw, const float* __restrict__ lb,
    float* __restrict__ out)
{
    extern __shared__ float smd[];
    float* hbn = smd;            // [32][256]
    float* lws = smd + 8192;     // [32][260]

    const int tid = threadIdx.x;
    const int lane = tid & 31, cq = tid >> 5;   // cq in [0,16)
    const int lt = blockIdx.x;   // l'-tile
    const int b = blockIdx.y;

    // hbn: BN + ReLU applied on load
    for (int idx = tid; idx < 8192; idx += 512) {
        int c = idx >> 8, l = idx & 255;
        float v = g_hbuf[(b * 32 + c) * 256 + l];
        hbn[idx] = fmaxf(v * g_scale[c] + g_shift[c], 0.f);
    }
    // lin_w tile rows l' = lt*32 + r, all 256 cols (coalesced)
    for (int idx = tid; idx < 8192; idx += 512) {
        int r = idx >> 8, col = idx & 255;
        lws[r * 260 + col] = lw[(lt * 32 + r) * 256 + col];
    }
    __syncthreads();

    const int c0 = cq * 2;
    ull acc[2] = {0, 0};
    const ulonglong2* wrow = (const ulonglong2*)&lws[lane * 260];
    const ulonglong2* h0 = (const ulonglong2*)&hbn[(c0 + 0) * 256];
    const ulonglong2* h1 = (const ulonglong2*)&hbn[(c0 + 1) * 256];
    #pragma unroll 8
    for (int l4 = 0; l4 < 64; l4++) {
        ulonglong2 w = wrow[l4];
        ulonglong2 a = h0[l4], bq = h1[l4];
        acc[0] = fma2(w.x, a.x,  acc[0]); acc[0] = fma2(w.y, a.y,  acc[0]);
        acc[1] = fma2(w.x, bq.x, acc[1]); acc[1] = fma2(w.y, bq.y, acc[1]);
    }

    const int lp = lt * 32 + lane;
    const float lbv = lb[lp];
    #pragma unroll
    for (int j = 0; j < 2; j++) {
        int base = (b * 32 + c0 + j) * 9;
        float p = hsum(acc[j]) + lbv;
        out[(base + 8) * 256 + lp] = out[(base + 2) * 256 + lp] - p;
    }
}

// ---------------------------------------------------------------------------
extern "C" void kernel_launch(void* const* d_in, const int* in_sizes, int n_in,
                              void* d_out, int out_size)
{
    const float* x     = (const float*)d_in[0];
    const float* qw    = (const float*)d_in[1];
    const float* qb    = (const float*)d_in[2];
    const float* kw    = (const float*)d_in[3];
    const float* kb    = (const float*)d_in[4];
    const float* vw    = (const float*)d_in[5];
    const float* vb    = (const float*)d_in[6];
    const float* mw    = (const float*)d_in[7];
    const float* mb    = (const float*)d_in[8];
    const float* pre   = (const float*)d_in[9];
    const float* cw    = (const float*)d_in[10];
    const float* cb    = (const float*)d_in[11];
    const float* gamma = (const float*)d_in[12];
    const float* beta  = (const float*)d_in[13];
    const float* lw    = (const float*)d_in[14];
    const float* lb    = (const float*)d_in[15];
    float* out = (float*)d_out;

    const int smemA = (8192 + 8192 + 4096 + 128 + 8704) * 4;  // 117248 B
    cudaFuncSetAttribute(k_attn, cudaFuncAttributeMaxDynamicSharedMemorySize, smemA);
    const int smemD = (8192 + 32 * 260) * 4;                  // 66048 B
    cudaFuncSetAttribute(k_lin, cudaFuncAttributeMaxDynamicSharedMemorySize, smemD);

    k_attn<<<128, 512, smemA>>>(x, qw, qb, kw, kb, vw, vb, mw, mb, out);
    k_conv<<<dim3(8, 16), 256>>>(out, pre, cw, cb);
    k_stats<<<32, 128>>>(gamma, beta);
    k_lin<<<dim3(8, 16), 512, smemD>>>(lw, lb, out);
}